// round 13
// baseline (speedup 1.0000x reference)
#include <cuda_runtime.h>
#include <cstdint>
#include <math.h>

// GRU: B=32, S=2048, E=256, H=256, fp32.
// Kernel 1: gate-input GEMMs xg = x @ {Wz,Wr,Wh}.
// Kernel 2: persistent scan, 16 groups x 8-CTA cluster, CTA owns 32-wide
//   j-slice; U in registers. Cluster exchange of h and r*h via
//   cp.async.bulk.shared::cluster (128-B payloads, 16 msgs/exchange)
//   instead of 256 scalar st.async -> kills mbarrier tx-update serialization.

#define SS   2048
#define EE   256
#define HH   256
#define CSZ  8
#define NB   2
#define NT   256
#define NGRP 16
#define GRID (NGRP * CSZ)
#define GM   (32 * 2048)

typedef unsigned long long u64;

__device__ float g_gates[(size_t)3 * GM * HH];   // [g][b*S+t][h]

// ---------------- helpers ----------------
__device__ __forceinline__ uint32_t smem_u32(const void* p) {
    uint32_t a;
    asm("{ .reg .u64 t; cvta.to.shared.u64 t, %1; cvt.u32.u64 %0, t; }"
        : "=r"(a) : "l"(p));
    return a;
}
__device__ __forceinline__ void mbar_init(uint32_t a, uint32_t cnt) {
    asm volatile("mbarrier.init.shared.b64 [%0], %1;" :: "r"(a), "r"(cnt) : "memory");
}
__device__ __forceinline__ void mbar_expect(uint32_t a, uint32_t bytes) {
    asm volatile("mbarrier.arrive.expect_tx.shared.b64 _, [%0], %1;"
                 :: "r"(a), "r"(bytes) : "memory");
}
__device__ __forceinline__ void mbar_wait(uint32_t a, uint32_t parity) {
    asm volatile(
        "{\n\t.reg .pred P1;\n\t"
        "WL_%=:\n\t"
        "mbarrier.try_wait.parity.acquire.cta.shared::cta.b64 P1, [%0], %1, 0x989680;\n\t"
        "@P1 bra.uni WD_%=;\n\t"
        "bra.uni WL_%=;\n\t"
        "WD_%=:\n\t}"
        :: "r"(a), "r"(parity) : "memory");
}
__device__ __forceinline__ void cluster_sync_() {
    asm volatile("barrier.cluster.arrive.aligned;" ::: "memory");
    asm volatile("barrier.cluster.wait.aligned;"  ::: "memory");
}
__device__ __forceinline__ u64 pk(float lo, float hi) {
    u64 r; asm("mov.b64 %0, {%1, %2};" : "=l"(r) : "f"(lo), "f"(hi)); return r;
}
__device__ __forceinline__ float hsum(u64 v) {
    float a, b; asm("mov.b64 {%0, %1}, %2;" : "=f"(a), "=f"(b) : "l"(v));
    return a + b;
}
__device__ __forceinline__ void ffma2(u64& d, u64 a, u64 b) {
    asm("fma.rn.f32x2 %0, %1, %2, %0;" : "+l"(d) : "l"(a), "l"(b));
}
// bulk copy local smem -> peer smem (cluster), tx-accounted at peer's mbarrier
__device__ __forceinline__ void bulk_to_peer(uint32_t dst_cluster, uint32_t src_cta,
                                             uint32_t bytes, uint32_t mbar_cluster) {
    asm volatile("cp.async.bulk.shared::cluster.shared::cta."
                 "mbarrier::complete_tx::bytes [%0], [%1], %2, [%3];"
                 :: "r"(dst_cluster), "r"(src_cta), "r"(bytes), "r"(mbar_cluster)
                 : "memory");
}
__device__ __forceinline__ void fence_async_() {
    asm volatile("fence.proxy.async.shared::cta;" ::: "memory");
}

// ================= Kernel 1: gate-input GEMMs =================
__global__ void __launch_bounds__(256)
gru_gemm(const float* __restrict__ x, const float* __restrict__ Wz,
         const float* __restrict__ Wr, const float* __restrict__ Wh)
{
    __shared__ float sA[32][128];
    __shared__ float sB[32][64];

    const int mt = blockIdx.x;
    const int gy = blockIdx.y;
    const int g  = gy >> 2, nt = gy & 3;
    const float* W = (g == 0) ? Wz : (g == 1) ? Wr : Wh;
    const int row0 = mt * 128, col0 = nt * 64;

    const int tid = threadIdx.x;
    const int tx = tid & 15;
    const int ty = tid >> 4;

    u64 acc[8][2];
#pragma unroll
    for (int i = 0; i < 8; i++) { acc[i][0] = 0; acc[i][1] = 0; }

    for (int kc = 0; kc < 8; kc++) {
#pragma unroll
        for (int q = 0; q < 4; q++) {
            const int fi = tid + q * 256;
            const int r  = fi >> 3, c = fi & 7;
            const float4 v = *(const float4*)&x[(size_t)(row0 + r) * EE + kc * 32 + c * 4];
            sA[c * 4 + 0][r] = v.x;
            sA[c * 4 + 1][r] = v.y;
            sA[c * 4 + 2][r] = v.z;
            sA[c * 4 + 3][r] = v.w;
        }
#pragma unroll
        for (int q = 0; q < 2; q++) {
            const int fi = tid + q * 256;
            const int r  = fi >> 4, c = fi & 15;
            *(float4*)&sB[r][c * 4] =
                *(const float4*)&W[(size_t)(kc * 32 + r) * HH + col0 + c * 4];
        }
        __syncthreads();
#pragma unroll 8
        for (int k = 0; k < 32; k++) {
            const float4 a0 = *(const float4*)&sA[k][ty * 8];
            const float4 a1 = *(const float4*)&sA[k][ty * 8 + 4];
            const u64 b0 = *(const u64*)&sB[k][tx * 4];
            const u64 b1 = *(const u64*)&sB[k][tx * 4 + 2];
            const float av[8] = {a0.x, a0.y, a0.z, a0.w, a1.x, a1.y, a1.z, a1.w};
#pragma unroll
            for (int i = 0; i < 8; i++) {
                const u64 a2 = pk(av[i], av[i]);
                ffma2(acc[i][0], a2, b0);
                ffma2(acc[i][1], a2, b1);
            }
        }
        __syncthreads();
    }
#pragma unroll
    for (int i = 0; i < 8; i++) {
        const size_t idx = ((size_t)g * GM + row0 + ty * 8 + i) * HH + col0 + tx * 4;
        *(u64*)&g_gates[idx]     = acc[i][0];
        *(u64*)&g_gates[idx + 2] = acc[i][1];
    }
}

// ================= Kernel 2: persistent scan =================
// smem floats. h/rh layout: [par][rank][b][32] -> sender slice contiguous 128B.
#define OFF_H    0      // [2][8][2][32] = 1024
#define OFF_RH   1024   // 1024
#define OFF_P    2048   // [6][256] = 1536
#define OFF_SRH  3584   // staging [2 par][2 b][32] = 128
#define OFF_SH   3712   // staging [2 par][2 b][32] = 128
#define OFF_MB   3840   // 4 mbarriers = 8 floats
#define SMEM_FLOATS (OFF_MB + 8)
#define SMEM_BYTES  (SMEM_FLOATS * 4)

extern __shared__ float smem[];

__global__ void __cluster_dims__(CSZ, 1, 1) __launch_bounds__(NT, 1)
gru_scan(const float* __restrict__ h0,
         const float* __restrict__ Uz, const float* __restrict__ Ur,
         const float* __restrict__ Uh, float* __restrict__ out)
{
    const int tid   = threadIdx.x;
    const int rank  = blockIdx.x & (CSZ - 1);
    const int grp   = blockIdx.x >> 3;
    const int b0    = grp * NB;
    const int jbase = rank * 32;
    const int j     = tid & 31;
    const int ks    = tid >> 5;
    const int k0    = ks * 32;
    const int jcol  = jbase + j;

    float* sP = smem + OFF_P;

    const uint32_t base_u = smem_u32(smem);
    const uint32_t mb_rh  = base_u + OFF_MB * 4;        // +par*8
    const uint32_t mb_h   = base_u + OFF_MB * 4 + 16;   // +par*8

    // U slices (rows k0..k0+31, column jcol), k-pairs packed for FFMA2.
    u64 uz2[16], ur2[16], uh2[16];
#pragma unroll
    for (int p = 0; p < 16; p++) {
        const int k = k0 + 2 * p;
        uz2[p] = pk(Uz[k * HH + jcol], Uz[(k + 1) * HH + jcol]);
        ur2[p] = pk(Ur[k * HH + jcol], Ur[(k + 1) * HH + jcol]);
        uh2[p] = pk(Uh[k * HH + jcol], Uh[(k + 1) * HH + jcol]);
    }
    // h0 into parity-0 buffer: layout [rank][b][32]
    smem[OFF_H + (tid >> 5) * 64 + (tid & 31)]      = h0[b0 * HH + tid];
    smem[OFF_H + (tid >> 5) * 64 + 32 + (tid & 31)] = h0[(b0 + 1) * HH + tid];
    if (tid == 0) {
        mbar_init(mb_rh, 1); mbar_init(mb_rh + 8, 1);
        mbar_init(mb_h, 1);  mbar_init(mb_h + 8, 1);
    }
    __syncthreads();
    cluster_sync_();

    // gate-input prefetch (role-partitioned)
    float pre_r = 0.f, pre_z = 0.f, pre_h = 0.f;
    if (tid < 64) {
        const int b = tid >> 5, jj = tid & 31;
        pre_r = g_gates[((size_t)1 * GM + (size_t)(b0 + b) * SS) * HH + jbase + jj];
    } else if (tid >= 128 && tid < 192) {
        const int b = (tid - 128) >> 5, jj = tid & 31;
        pre_z = g_gates[((size_t)0 * GM + (size_t)(b0 + b) * SS) * HH + jbase + jj];
        pre_h = g_gates[((size_t)2 * GM + (size_t)(b0 + b) * SS) * HH + jbase + jj];
    }

    for (int t = 0; t < SS; t++) {
        const int par = t & 1;
        const int nxt = par ^ 1;
        // h/rh views for this parity (u64 k-pair pointers per thread's k-chunk)
        const u64* Hb0 = (const u64*)(smem + OFF_H  + par * 512 + ks * 64);
        const u64* Hb1 = Hb0 + 16;
        const u64* Rb0 = (const u64*)(smem + OFF_RH + par * 512 + ks * 64);
        const u64* Rb1 = Rb0 + 16;
        float* shOwn = smem + OFF_H + par * 512 + rank * 64;   // [b][32] own slice

        if (tid == 0) {
            mbar_expect(mb_rh + par * 8, 2048);
            if (t + 1 < SS) mbar_expect(mb_h + nxt * 8, 2048);
        }
        if (t > 0) mbar_wait(mb_h + par * 8, (uint32_t)(((t - 2 + par) >> 1) & 1));

        // ---- phase R: h @ Ur (partial over own k-chunk) ----
        u64 ar0 = 0, ar1 = 0;
#pragma unroll
        for (int p = 0; p < 16; p++) {
            ffma2(ar0, Hb0[p], ur2[p]);
            ffma2(ar1, Hb1[p], ur2[p]);
        }
        sP[tid]       = hsum(ar0);
        sP[256 + tid] = hsum(ar1);
        __syncthreads();

        // ---- r reduce + bulk-push r*h slice (warps 0,1; b = warp) ----
        if (tid < 64) {
            const int b = tid >> 5, jj = tid & 31;
            float s = pre_r;
#pragma unroll
            for (int q = 0; q < 8; q++) s += sP[b * 256 + q * 32 + jj];
            const float r  = __fdividef(1.f, 1.f + __expf(-s));
            const float rh = r * shOwn[b * 32 + jj];
            smem[OFF_SRH + par * 64 + b * 32 + jj] = rh;       // stage
            __syncwarp();
            fence_async_();
            if (jj == 0) {
                const uint32_t src = base_u + (uint32_t)(OFF_SRH + par * 64 + b * 32) * 4;
                const uint32_t dof = (uint32_t)(OFF_RH + par * 512 + rank * 64 + b * 32) * 4;
                const uint32_t mof = (uint32_t)(OFF_MB * 4) + (uint32_t)(par * 8);
#pragma unroll
                for (int rr = 0; rr < CSZ; rr++) {
                    uint32_t pa;
                    asm volatile("mapa.shared::cluster.u32 %0, %1, %2;"
                                 : "=r"(pa) : "r"(base_u), "r"(rr));
                    bulk_to_peer(pa + dof, src, 128, pa + mof);
                }
            }
            if (t + 1 < SS)
                pre_r = g_gates[((size_t)1 * GM + (size_t)(b0 + b) * SS + t + 1) * HH
                                + jbase + jj];
        }

        // ---- phase Z: h @ Uz (hides rh flight) ----
        u64 az0 = 0, az1 = 0;
#pragma unroll
        for (int p = 0; p < 16; p++) {
            ffma2(az0, Hb0[p], uz2[p]);
            ffma2(az1, Hb1[p], uz2[p]);
        }
        sP[512 + tid] = hsum(az0);
        sP[768 + tid] = hsum(az1);

        mbar_wait(mb_rh + par * 8, (uint32_t)((t >> 1) & 1));

        // ---- phase H: (r*h) @ Uh ----
        u64 ah0 = 0, ah1 = 0;
#pragma unroll
        for (int p = 0; p < 16; p++) {
            ffma2(ah0, Rb0[p], uh2[p]);
            ffma2(ah1, Rb1[p], uh2[p]);
        }
        sP[1024 + tid] = hsum(ah0);
        sP[1280 + tid] = hsum(ah1);
        __syncthreads();

        // ---- combine + bulk-push h(t+1) slice (warps 4,5; b = warp-4) ----
        if (tid >= 128 && tid < 192) {
            const int b = (tid - 128) >> 5, jj = tid & 31;
            float sz = pre_z, sh = pre_h;
#pragma unroll
            for (int q = 0; q < 8; q++) {
                sz += sP[(2 + b) * 256 + q * 32 + jj];
                sh += sP[(4 + b) * 256 + q * 32 + jj];
            }
            const float z    = __fdividef(1.f, 1.f + __expf(-sz));
            const float hw   = 1.f - __fdividef(2.f, __expf(2.f * sh) + 1.f);
            const float hold = shOwn[b * 32 + jj];
            const float hnew = fmaf(z, hw - hold, hold);
            out[((size_t)(b0 + b) * SS + t) * HH + jbase + jj] = hnew;
            if (t + 1 < SS) {
                smem[OFF_SH + nxt * 64 + b * 32 + jj] = hnew;  // stage
                __syncwarp();
                fence_async_();
                if (jj == 0) {
                    const uint32_t src = base_u + (uint32_t)(OFF_SH + nxt * 64 + b * 32) * 4;
                    const uint32_t dof = (uint32_t)(OFF_H + nxt * 512 + rank * 64 + b * 32) * 4;
                    const uint32_t mof = (uint32_t)(OFF_MB * 4 + 16) + (uint32_t)(nxt * 8);
#pragma unroll
                    for (int rr = 0; rr < CSZ; rr++) {
                        uint32_t pa;
                        asm volatile("mapa.shared::cluster.u32 %0, %1, %2;"
                                     : "=r"(pa) : "r"(base_u), "r"(rr));
                        bulk_to_peer(pa + dof, src, 128, pa + mof);
                    }
                }
                pre_z = g_gates[((size_t)0 * GM + (size_t)(b0 + b) * SS + t + 1) * HH
                                + jbase + jj];
                pre_h = g_gates[((size_t)2 * GM + (size_t)(b0 + b) * SS + t + 1) * HH
                                + jbase + jj];
            }
        }
    }
    cluster_sync_();   // no CTA exits while inbound traffic could be in flight
}

extern "C" void kernel_launch(void* const* d_in, const int* in_sizes, int n_in,
                              void* d_out, int out_size)
{
    (void)in_sizes; (void)n_in; (void)out_size;
    const float* x  = (const float*)d_in[0];
    const float* h0 = (const float*)d_in[1];
    const float* Wz = (const float*)d_in[2];
    const float* Uz = (const float*)d_in[3];
    const float* Wr = (const float*)d_in[4];
    const float* Ur = (const float*)d_in[5];
    const float* Wh = (const float*)d_in[6];
    const float* Uh = (const float*)d_in[7];
    float* out = (float*)d_out;

    dim3 ggrid(512, 12);
    gru_gemm<<<ggrid, 256>>>(x, Wz, Wr, Wh);

    cudaFuncSetAttribute(gru_scan,
                         cudaFuncAttributeMaxDynamicSharedMemorySize, SMEM_BYTES);
    gru_scan<<<GRID, NT, SMEM_BYTES>>>(h0, Uz, Ur, Uh, out);
}

// round 15
// speedup vs baseline: 1.8388x; 1.8388x over previous
#include <cuda_runtime.h>
#include <cstdint>
#include <math.h>

// GRU: B=32, S=2048, E=256, H=256, fp32.
// Kernel 1: gate-input GEMMs xg = x @ {Wz,Wr,Wh}.
// Kernel 2: persistent scan, 8 groups x 8-CTA cluster, 4 batches per group
//   as TWO independent streams (P,Q) interleaved so each stream's DSMEM
//   flights are hidden behind the other stream's compute. U in registers
//   (shared by both streams). j-slice ownership as round 11.

#define SS   2048
#define EE   256
#define HH   256
#define CSZ  8
#define NT   256
#define NGRP 8
#define GRID (NGRP * CSZ)
#define GM   (32 * 2048)

typedef unsigned long long u64;

__device__ float g_gates[(size_t)3 * GM * HH];   // [g][b*S+t][h]

// ---------------- helpers ----------------
__device__ __forceinline__ uint32_t smem_u32(const void* p) {
    uint32_t a;
    asm("{ .reg .u64 t; cvta.to.shared.u64 t, %1; cvt.u32.u64 %0, t; }"
        : "=r"(a) : "l"(p));
    return a;
}
__device__ __forceinline__ void mbar_init(uint32_t a, uint32_t cnt) {
    asm volatile("mbarrier.init.shared.b64 [%0], %1;" :: "r"(a), "r"(cnt) : "memory");
}
__device__ __forceinline__ void mbar_expect(uint32_t a, uint32_t bytes) {
    asm volatile("mbarrier.arrive.expect_tx.shared.b64 _, [%0], %1;"
                 :: "r"(a), "r"(bytes) : "memory");
}
__device__ __forceinline__ void mbar_wait(uint32_t a, uint32_t parity) {
    asm volatile(
        "{\n\t.reg .pred P1;\n\t"
        "WL_%=:\n\t"
        "mbarrier.try_wait.parity.acquire.cta.shared::cta.b64 P1, [%0], %1, 0x989680;\n\t"
        "@P1 bra.uni WD_%=;\n\t"
        "bra.uni WL_%=;\n\t"
        "WD_%=:\n\t}"
        :: "r"(a), "r"(parity) : "memory");
}
__device__ __forceinline__ void cluster_sync_() {
    asm volatile("barrier.cluster.arrive.aligned;" ::: "memory");
    asm volatile("barrier.cluster.wait.aligned;"  ::: "memory");
}
__device__ __forceinline__ u64 pk(float lo, float hi) {
    u64 r; asm("mov.b64 %0, {%1, %2};" : "=l"(r) : "f"(lo), "f"(hi)); return r;
}
__device__ __forceinline__ float hsum(u64 v) {
    float a, b; asm("mov.b64 {%0, %1}, %2;" : "=f"(a), "=f"(b) : "l"(v));
    return a + b;
}
__device__ __forceinline__ void ffma2(u64& d, u64 a, u64 b) {
    asm("fma.rn.f32x2 %0, %1, %2, %0;" : "+l"(d) : "l"(a), "l"(b));
}
// send packed 8B to same smem offset in all cluster CTAs; moff_b is the BYTE
// OFFSET (from each CTA's smem base) of the tx-accounting mbarrier.
__device__ __forceinline__ void push8_b64(uint32_t base_u, uint32_t off_b,
                                          u64 v, uint32_t moff_b) {
#pragma unroll
    for (int r = 0; r < CSZ; r++) {
        uint32_t ra;
        asm volatile("mapa.shared::cluster.u32 %0, %1, %2;"
                     : "=r"(ra) : "r"(base_u), "r"(r));
        asm volatile("st.async.shared::cluster.mbarrier::complete_tx::bytes.b64 "
                     "[%0], %1, [%2];"
                     :: "r"(ra + off_b), "l"(v), "r"(ra + moff_b) : "memory");
    }
}

// ================= Kernel 1: gate-input GEMMs =================
__global__ void __launch_bounds__(256)
gru_gemm(const float* __restrict__ x, const float* __restrict__ Wz,
         const float* __restrict__ Wr, const float* __restrict__ Wh)
{
    __shared__ float sA[32][128];
    __shared__ float sB[32][64];

    const int mt = blockIdx.x;
    const int gy = blockIdx.y;
    const int g  = gy >> 2, nt = gy & 3;
    const float* W = (g == 0) ? Wz : (g == 1) ? Wr : Wh;
    const int row0 = mt * 128, col0 = nt * 64;

    const int tid = threadIdx.x;
    const int tx = tid & 15;
    const int ty = tid >> 4;

    u64 acc[8][2];
#pragma unroll
    for (int i = 0; i < 8; i++) { acc[i][0] = 0; acc[i][1] = 0; }

    for (int kc = 0; kc < 8; kc++) {
#pragma unroll
        for (int q = 0; q < 4; q++) {
            const int fi = tid + q * 256;
            const int r  = fi >> 3, c = fi & 7;
            const float4 v = *(const float4*)&x[(size_t)(row0 + r) * EE + kc * 32 + c * 4];
            sA[c * 4 + 0][r] = v.x;
            sA[c * 4 + 1][r] = v.y;
            sA[c * 4 + 2][r] = v.z;
            sA[c * 4 + 3][r] = v.w;
        }
#pragma unroll
        for (int q = 0; q < 2; q++) {
            const int fi = tid + q * 256;
            const int r  = fi >> 4, c = fi & 15;
            *(float4*)&sB[r][c * 4] =
                *(const float4*)&W[(size_t)(kc * 32 + r) * HH + col0 + c * 4];
        }
        __syncthreads();
#pragma unroll 8
        for (int k = 0; k < 32; k++) {
            const float4 a0 = *(const float4*)&sA[k][ty * 8];
            const float4 a1 = *(const float4*)&sA[k][ty * 8 + 4];
            const u64 b0 = *(const u64*)&sB[k][tx * 4];
            const u64 b1 = *(const u64*)&sB[k][tx * 4 + 2];
            const float av[8] = {a0.x, a0.y, a0.z, a0.w, a1.x, a1.y, a1.z, a1.w};
#pragma unroll
            for (int i = 0; i < 8; i++) {
                const u64 a2 = pk(av[i], av[i]);
                ffma2(acc[i][0], a2, b0);
                ffma2(acc[i][1], a2, b1);
            }
        }
        __syncthreads();
    }
#pragma unroll
    for (int i = 0; i < 8; i++) {
        const size_t idx = ((size_t)g * GM + row0 + ty * 8 + i) * HH + col0 + tx * 4;
        *(u64*)&g_gates[idx]     = acc[i][0];
        *(u64*)&g_gates[idx + 2] = acc[i][1];
    }
}

// ================= Kernel 2: persistent scan, dual-stream =================
// smem floats:
//  h  [par][str][b][256] = 2048
//  rh [par][str][b][256] = 2048
//  sP: R [str][b][256] = 1024; Z at +1024; H at +2048 -> 3072 total
//  mbars: rh[str*2+par] (4) then h[str*2+par] (4) = 16 floats
#define OFF_H   0
#define OFF_RH  2048
#define OFF_P   4096
#define OFF_MB  7168
#define MB_RH_B  (OFF_MB * 4)         // byte offset of rh mbarriers
#define MB_H_B   (OFF_MB * 4 + 32)    // byte offset of h  mbarriers
#define SMEM_FLOATS (OFF_MB + 16)
#define SMEM_BYTES  (SMEM_FLOATS * 4)

extern __shared__ float smem[];

__global__ void __cluster_dims__(CSZ, 1, 1) __launch_bounds__(NT, 1)
gru_scan(const float* __restrict__ h0,
         const float* __restrict__ Uz, const float* __restrict__ Ur,
         const float* __restrict__ Uh, float* __restrict__ out)
{
    const int tid   = threadIdx.x;
    const int rank  = blockIdx.x & (CSZ - 1);
    const int grp   = blockIdx.x >> 3;
    const int b0g   = grp * 4;                 // 4 batches per group
    const int jbase = rank * 32;
    const int j     = tid & 31;
    const int ks    = tid >> 5;
    const int k0    = ks * 32;
    const int ks16  = ks * 16;
    const int jcol  = jbase + j;

    float* sP = smem + OFF_P;

    const uint32_t base_u = smem_u32(smem);

    // U slices (rows k0..k0+31, column jcol), k-pairs packed for FFMA2.
    u64 uz2[16], ur2[16], uh2[16];
#pragma unroll
    for (int p = 0; p < 16; p++) {
        const int k = k0 + 2 * p;
        uz2[p] = pk(Uz[k * HH + jcol], Uz[(k + 1) * HH + jcol]);
        ur2[p] = pk(Ur[k * HH + jcol], Ur[(k + 1) * HH + jcol]);
        uh2[p] = pk(Uh[k * HH + jcol], Uh[(k + 1) * HH + jcol]);
    }
    // h0 into parity-0 buffers (both streams); layout [par][str][b][256]
#pragma unroll
    for (int sb = 0; sb < 4; sb++) {   // sb = s*2+b
        smem[OFF_H + sb * 256 + tid] = h0[(b0g + sb) * HH + tid];
    }
    if (tid == 0) {
#pragma unroll
        for (int i = 0; i < 8; i++)
            mbar_init(base_u + MB_RH_B + i * 8, 1);   // 4 rh then 4 h (contiguous)
    }
    __syncthreads();
    cluster_sync_();

    // gate-input prefetch (role-partitioned).
    float pre_r = 0.f, pre_z = 0.f, pre_h = 0.f;
    if (tid < 128) {
        const int s = tid >> 6, b = (tid >> 5) & 1, jj = tid & 31;
        pre_r = g_gates[((size_t)1 * GM + (size_t)(b0g + s * 2 + b) * SS) * HH + jbase + jj];
    } else {
        const int m = tid - 128;
        const int s = m >> 6, b = (m >> 5) & 1, jj = tid & 31;
        pre_z = g_gates[((size_t)0 * GM + (size_t)(b0g + s * 2 + b) * SS) * HH + jbase + jj];
        pre_h = g_gates[((size_t)2 * GM + (size_t)(b0g + s * 2 + b) * SS) * HH + jbase + jj];
    }

    for (int t = 0; t < SS; t++) {
        const int par = t & 1;
        const int nxt = par ^ 1;
        const uint32_t prh = (uint32_t)((t >> 1) & 1);
        const uint32_t ph  = (uint32_t)(((t - 2 + par) >> 1) & 1);

        if (tid == 0) {
#pragma unroll
            for (int s = 0; s < 2; s++) {
                mbar_expect(base_u + MB_RH_B + (s * 2 + par) * 8, 2048);
                if (t + 1 < SS)
                    mbar_expect(base_u + MB_H_B + (s * 2 + nxt) * 8, 2048);
            }
        }

        // ---- phase R for both streams (wait h, matvec) ----
#pragma unroll
        for (int s = 0; s < 2; s++) {
            if (t > 0) mbar_wait(base_u + MB_H_B + (s * 2 + par) * 8, ph);
            const u64* Hb0 = (const u64*)(smem + OFF_H + (par * 2 + s) * 512);
            const u64* Hb1 = Hb0 + 128;
            u64 a0 = 0, a1 = 0;
#pragma unroll
            for (int p = 0; p < 16; p++) {
                ffma2(a0, Hb0[ks16 + p], ur2[p]);
                ffma2(a1, Hb1[ks16 + p], ur2[p]);
            }
            sP[s * 512 + tid]       = hsum(a0);
            sP[s * 512 + 256 + tid] = hsum(a1);
        }
        __syncthreads();

        // ---- reduce warps 0-3: r gate, rh push (P: w0-1, Q: w2-3) ----
        if (tid < 128) {
            const int s = tid >> 6, b = (tid >> 5) & 1, jj = tid & 31;
            float sum = pre_r;
#pragma unroll
            for (int q = 0; q < 8; q++) sum += sP[s * 512 + b * 256 + q * 32 + jj];
            const float r  = __fdividef(1.f, 1.f + __expf(-sum));
            const float rh = r * smem[OFF_H + ((par * 2 + s) * 2 + b) * 256 + jbase + jj];
            const float rhh = __shfl_down_sync(0xffffffffu, rh, 1);
            if ((jj & 1) == 0) {
                const uint32_t off =
                    (uint32_t)(OFF_RH + ((par * 2 + s) * 2 + b) * 256 + jbase + jj) * 4;
                push8_b64(base_u, off, pk(rh, rhh),
                          (uint32_t)(MB_RH_B + (s * 2 + par) * 8));
            }
            if (t + 1 < SS)
                pre_r = g_gates[((size_t)1 * GM + (size_t)(b0g + s * 2 + b) * SS + t + 1) * HH
                                + jbase + jj];
        }

        // ---- phase Z for both streams (hides rh flights) ----
#pragma unroll
        for (int s = 0; s < 2; s++) {
            const u64* Hb0 = (const u64*)(smem + OFF_H + (par * 2 + s) * 512);
            const u64* Hb1 = Hb0 + 128;
            u64 a0 = 0, a1 = 0;
#pragma unroll
            for (int p = 0; p < 16; p++) {
                ffma2(a0, Hb0[ks16 + p], uz2[p]);
                ffma2(a1, Hb1[ks16 + p], uz2[p]);
            }
            sP[1024 + s * 512 + tid]       = hsum(a0);
            sP[1024 + s * 512 + 256 + tid] = hsum(a1);
        }

        // ---- phase H for both streams (wait rh, matvec) ----
#pragma unroll
        for (int s = 0; s < 2; s++) {
            mbar_wait(base_u + MB_RH_B + (s * 2 + par) * 8, prh);
            const u64* Rb0 = (const u64*)(smem + OFF_RH + (par * 2 + s) * 512);
            const u64* Rb1 = Rb0 + 128;
            u64 a0 = 0, a1 = 0;
#pragma unroll
            for (int p = 0; p < 16; p++) {
                ffma2(a0, Rb0[ks16 + p], uh2[p]);
                ffma2(a1, Rb1[ks16 + p], uh2[p]);
            }
            sP[2048 + s * 512 + tid]       = hsum(a0);
            sP[2048 + s * 512 + 256 + tid] = hsum(a1);
        }
        __syncthreads();

        // ---- combine warps 4-7: z, h~, out, h push (P: w4-5, Q: w6-7) ----
        if (tid >= 128) {
            const int m = tid - 128;
            const int s = m >> 6, b = (m >> 5) & 1, jj = tid & 31;
            float sz = pre_z, sh = pre_h;
#pragma unroll
            for (int q = 0; q < 8; q++) {
                sz += sP[1024 + s * 512 + b * 256 + q * 32 + jj];
                sh += sP[2048 + s * 512 + b * 256 + q * 32 + jj];
            }
            const float z    = __fdividef(1.f, 1.f + __expf(-sz));
            const float hw   = 1.f - __fdividef(2.f, __expf(2.f * sh) + 1.f);
            const float hold = smem[OFF_H + ((par * 2 + s) * 2 + b) * 256 + jbase + jj];
            const float hnew = fmaf(z, hw - hold, hold);
            out[((size_t)(b0g + s * 2 + b) * SS + t) * HH + jbase + jj] = hnew;
            if (t + 1 < SS) {
                const float hh = __shfl_down_sync(0xffffffffu, hnew, 1);
                if ((jj & 1) == 0) {
                    const uint32_t off =
                        (uint32_t)(OFF_H + ((nxt * 2 + s) * 2 + b) * 256 + jbase + jj) * 4;
                    push8_b64(base_u, off, pk(hnew, hh),
                              (uint32_t)(MB_H_B + (s * 2 + nxt) * 8));
                }
                pre_z = g_gates[((size_t)0 * GM + (size_t)(b0g + s * 2 + b) * SS + t + 1) * HH
                                + jbase + jj];
                pre_h = g_gates[((size_t)2 * GM + (size_t)(b0g + s * 2 + b) * SS + t + 1) * HH
                                + jbase + jj];
            }
        }
    }
    cluster_sync_();   // no CTA exits while inbound traffic could be in flight
}

extern "C" void kernel_launch(void* const* d_in, const int* in_sizes, int n_in,
                              void* d_out, int out_size)
{
    (void)in_sizes; (void)n_in; (void)out_size;
    const float* x  = (const float*)d_in[0];
    const float* h0 = (const float*)d_in[1];
    const float* Wz = (const float*)d_in[2];
    const float* Uz = (const float*)d_in[3];
    const float* Wr = (const float*)d_in[4];
    const float* Ur = (const float*)d_in[5];
    const float* Wh = (const float*)d_in[6];
    const float* Uh = (const float*)d_in[7];
    float* out = (float*)d_out;

    dim3 ggrid(512, 12);
    gru_gemm<<<ggrid, 256>>>(x, Wz, Wr, Wh);

    cudaFuncSetAttribute(gru_scan,
                         cudaFuncAttributeMaxDynamicSharedMemorySize, SMEM_BYTES);
    gru_scan<<<GRID, NT, SMEM_BYTES>>>(h0, Uz, Ur, Uh, out);
}